// round 6
// baseline (speedup 1.0000x reference)
#include <cuda_runtime.h>
#include <cuda_bf16.h>

// Fused Conv3d(8->8, k=3, same zero-pad) + sigmoid(gelu_tanh(relu(y))) + bias
// B=8, D=32, H=128, W=128. fp32, packed f32x2 FMAs.
//
// Round-6: software-pipelined staging.
//  - sC double-buffered, filled by cp.async.cg (LDGSTS: no register transit,
//    L1-bypass); the load for slab s+1 is issued before computing slab s,
//    hiding the full GMEM round trip behind ~2300 cycles of FMA work.
//  - sS (W-shifted copy, zero pads baked in) rebuilt per slab from sC via
//    LDS.128 -> shfl -> STS.128 (aligned, conflict-free).
//  - weights in __constant__ (uniform const port).

#define ROWP 132   // padded row stride in floats (528B = 33*16B)

typedef unsigned long long u64;

__constant__ __align__(16) u64 cW[1728];     // splatted (w,w), [(ci*3+kd)*3+kh][kw*8+co]
__device__   __align__(16) u64 gW_buf[1728]; // staging buffer for the memcpy node

__device__ __forceinline__ void fma2(u64& d, u64 a, u64 b) {
    asm("fma.rn.f32x2 %0, %1, %2, %0;" : "+l"(d) : "l"(a), "l"(b));
}
__device__ __forceinline__ u64 pk2(float lo, float hi) {
    u64 r;
    asm("mov.b64 %0, {%1, %2};" : "=l"(r) : "f"(lo), "f"(hi));
    return r;
}
__device__ __forceinline__ float2 up2(u64 v) {
    float lo, hi;
    asm("mov.b64 {%0, %1}, %2;" : "=f"(lo), "=f"(hi) : "l"(v));
    return make_float2(lo, hi);
}

// sigmoid(gelu_tanh(relu(y))): for yr=relu(y)>=0,
//   gelu = 0.5*yr*(1+tanh(t)) = yr * sigmoid(2t),  t = 0.79788456*(yr + 0.044715*yr^3)
__device__ __forceinline__ float act_chain(float y) {
    float yr = fmaxf(y, 0.0f);
    float q  = fmaf(0.044715f * yr, yr, 1.0f);
    float t2 = 1.5957691216057308f * yr * q;          // 2*t
    float g  = yr * __fdividef(1.0f, 1.0f + __expf(-t2));
    return __fdividef(1.0f, 1.0f + __expf(-g));
}

__global__ void weight_splat_kernel(const float* __restrict__ wgt) {
    for (int i = threadIdx.x; i < 1728; i += 256) {
        int co  = i / 216;  int rem = i - co * 216;
        int ci  = rem / 27; int r2  = rem - ci * 27;
        int kd  = r2 / 9;   int r3  = r2 - kd * 9;
        int kh  = r3 / 3;   int kw  = r3 - kh * 3;
        float w = wgt[i];   // layout [co][ci][kd][kh][kw] linear == i
        gW_buf[((ci * 3 + kd) * 3 + kh) * 24 + kw * 8 + co] = pk2(w, w);
    }
}

// issue cp.async for one 18x128 slice (ci, dd) into dstbuf
__device__ __forceinline__ void stage_issue(float* dstbuf, const float* __restrict__ x,
                                            int b, int ci, int dd, int h0, int tid) {
    const float4* xs4 = reinterpret_cast<const float4*>(
        x + ((size_t)((b * 8 + ci) * 32 + dd) << 14));
    #pragma unroll
    for (int j = 0; j < 3; ++j) {
        int i = tid + j * 256;                 // 0..767, 576 valid
        if (j < 2 || i < 576) {
            int hz = i >> 5, l4 = i & 31;
            int hg = h0 + hz - 1;
            bool ok = (unsigned)hg < 128u;
            const float4* src = xs4 + ((ok ? hg : 0) << 5) + l4;
            unsigned dst = (unsigned)__cvta_generic_to_shared(dstbuf + hz * ROWP + (l4 << 2));
            int nbytes = ok ? 16 : 0;          // 0 => zero-fill (H pad)
            asm volatile("cp.async.cg.shared.global [%0], [%1], 16, %2;"
                         :: "r"(dst), "l"(src), "r"(nbytes));
        }
    }
}

__global__ void __launch_bounds__(256, 2)
conv3d_fused_kernel(const float* __restrict__ x,
                    const float* __restrict__ bias,
                    float* __restrict__ out)
{
    __shared__ __align__(16) float sC[2][18 * ROWP];   // double-buffered x[r][w]
    __shared__ __align__(16) float sS[18 * ROWP];      // sS[r][k] = x[r][k-1]

    const int tid  = threadIdx.x;
    const int lane = tid & 31;
    const int warp = tid >> 5;
    const int bx   = blockIdx.x;
    const int ht   = bx & 7;
    const int dpos = (bx >> 3) & 31;
    const int b    = bx >> 8;
    const int h0   = ht << 4;

    // k=129 pad of the shifted copy (never rewritten)
    if (tid < 18) sS[tid * ROWP + 129] = 0.0f;

    const int hh = tid >> 4;     // row in tile (0..15)
    const int wg = tid & 15;
    const int w0 = wg << 3;

    u64 acc[32];
    #pragma unroll
    for (int k = 0; k < 32; ++k) acc[k] = 0ull;

    // valid depth-tap range (uniform per CTA)
    const int dzlo = (dpos == 0)  ? 1 : 0;
    const int dzhi = (dpos == 31) ? 2 : 3;
    const int ndz  = dzhi - dzlo;
    const int nslab = 8 * ndz;

    // issue slab 0
    int ici = 0, idz = dzlo;
    stage_issue(sC[0], x, b, ici, dpos + idz - 1, h0, tid);
    asm volatile("cp.async.commit_group;");
    if (++idz == dzhi) { idz = dzlo; ++ici; }

    int cci = 0, cdz = dzlo;
    for (int s = 0; s < nslab; ++s) {
        const int p = s & 1;
        float* scb = sC[p];

        asm volatile("cp.async.wait_group 0;");   // slab s landed
        __syncthreads();                          // + all warps done with slab s-1

        if (s + 1 < nslab) {                      // prefetch slab s+1 (overlaps below)
            stage_issue(sC[1 - p], x, b, ici, dpos + idz - 1, h0, tid);
            asm volatile("cp.async.commit_group;");
            if (++idz == dzhi) { idz = dzlo; ++ici; }
        }

        // build sS[k+1] = scb[k] via lane rotation (aligned LDS/STS.128)
        #pragma unroll
        for (int j = 0; j < 3; ++j) {
            int hz = warp + j * 8;                // 0..23, valid <18
            float4 v = make_float4(0.f, 0.f, 0.f, 0.f);
            if (hz < 18)
                v = *reinterpret_cast<const float4*>(&scb[hz * ROWP + (lane << 2)]);
            float pw = __shfl_up_sync(0xffffffffu, v.w, 1);
            if (lane == 0) pw = 0.0f;             // x[-1] zero pad
            if (hz < 18) {
                *reinterpret_cast<float4*>(&sS[hz * ROWP + (lane << 2)]) =
                    make_float4(pw, v.x, v.y, v.z);
                if (lane == 31) sS[hz * ROWP + 128] = v.w;   // sS[128] = x[127]
            }
        }
        __syncthreads();

        // hot loop: slab (cci, cdz)
        #pragma unroll
        for (int kh = 0; kh < 3; ++kh) {
            const int roff = (hh + kh) * ROWP;
            const ulonglong2* cp = reinterpret_cast<const ulonglong2*>(&scb[roff + w0]);
            ulonglong2 ca = cp[0];    // center pairs 0,1
            ulonglong2 cb = cp[1];    // center pairs 2,3
            const ulonglong2* sp = reinterpret_cast<const ulonglong2*>(&sS[roff + w0]);
            ulonglong2 sa = sp[0];    // left pairs 0,1
            ulonglong2 sb = sp[1];    // left pairs 2,3
            u64 sr3 = *reinterpret_cast<const u64*>(&sS[roff + w0 + 8]); // right pair 3

            const u64* wp = &cW[((cci * 3 + cdz) * 3 + kh) * 24];
            #pragma unroll
            for (int cp2 = 0; cp2 < 4; ++cp2) {   // co pairs (2 couts each)
                ulonglong2 wL = *reinterpret_cast<const ulonglong2*>(wp + 2 * cp2);
                ulonglong2 wC = *reinterpret_cast<const ulonglong2*>(wp + 8 + 2 * cp2);
                ulonglong2 wR = *reinterpret_cast<const ulonglong2*>(wp + 16 + 2 * cp2);
                u64* a0 = &acc[(2 * cp2) * 4];
                u64* a1 = &acc[(2 * cp2 + 1) * 4];
                fma2(a0[0], sa.x, wL.x);  fma2(a0[1], sa.y, wL.x);
                fma2(a0[2], sb.x, wL.x);  fma2(a0[3], sb.y, wL.x);
                fma2(a0[0], ca.x, wC.x);  fma2(a0[1], ca.y, wC.x);
                fma2(a0[2], cb.x, wC.x);  fma2(a0[3], cb.y, wC.x);
                fma2(a0[0], sa.y, wR.x);  fma2(a0[1], sb.x, wR.x);
                fma2(a0[2], sb.y, wR.x);  fma2(a0[3], sr3, wR.x);
                fma2(a1[0], sa.x, wL.y);  fma2(a1[1], sa.y, wL.y);
                fma2(a1[2], sb.x, wL.y);  fma2(a1[3], sb.y, wL.y);
                fma2(a1[0], ca.x, wC.y);  fma2(a1[1], ca.y, wC.y);
                fma2(a1[2], cb.x, wC.y);  fma2(a1[3], cb.y, wC.y);
                fma2(a1[0], sa.y, wR.y);  fma2(a1[1], sb.x, wR.y);
                fma2(a1[2], sb.y, wR.y);  fma2(a1[3], sr3, wR.y);
            }
        }

        if (++cdz == dzhi) { cdz = dzlo; ++cci; }
    }

    // --- epilogue: activation chain + bias, vectorized coalesced stores ---
    const int hout = h0 + hh;
    #pragma unroll
    for (int co = 0; co < 8; ++co) {
        float bb = bias[co];
        float o[8];
        #pragma unroll
        for (int j = 0; j < 4; ++j) {
            float2 p = up2(acc[co * 4 + j]);
            o[2 * j]     = p.x;
            o[2 * j + 1] = p.y;
        }
        #pragma unroll
        for (int k = 0; k < 8; ++k)
            o[k] = act_chain(o[k]) + bb;

        float4* dst = reinterpret_cast<float4*>(
            out + ((size_t)((b * 8 + co) * 32 + dpos) << 14) + (hout << 7) + w0);
        dst[0] = make_float4(o[0], o[1], o[2], o[3]);
        dst[1] = make_float4(o[4], o[5], o[6], o[7]);
    }
}

extern "C" void kernel_launch(void* const* d_in, const int* in_sizes, int n_in,
                              void* d_out, int out_size)
{
    const float* x    = (const float*)d_in[0];   // (8,8,32,128,128)
    const float* wgt  = (const float*)d_in[1];   // (8,8,3,3,3)
    const float* bias = (const float*)d_in[2];   // (8,1,1,1)
    float* out = (float*)d_out;                  // (8,8,32,128,128)

    weight_splat_kernel<<<1, 256>>>(wgt);
    void* gw_ptr = nullptr;
    cudaGetSymbolAddress(&gw_ptr, gW_buf);
    cudaMemcpyToSymbolAsync(cW, gw_ptr, 1728 * sizeof(u64), 0,
                            cudaMemcpyDeviceToDevice, 0);
    conv3d_fused_kernel<<<2048, 256>>>(x, bias, out);
}

// round 7
// speedup vs baseline: 1.8031x; 1.8031x over previous
#include <cuda_runtime.h>
#include <cuda_bf16.h>

// Fused Conv3d(8->8, k=3, same zero-pad) + sigmoid(gelu_tanh(relu(y))) + bias
// B=8, D=32, H=128, W=128. fp32, packed f32x2 FMAs.
//
// Round-7: revert to R5 structure (cp.async pipeline regressed). Change:
// 128-thread CTAs over 8-row H tiles -> 4 CTAs/SM (same 16 warps/SM) giving
// 4 independent staging/barrier domains per SM, so staging stalls of one CTA
// are covered by the other three. Inner loop / staging mechanics identical:
//  - single-pass staging (LDG.128 + shfl rotation -> sC and W-shifted sS)
//  - weights in __constant__ (uniform const port)
//  - all fma.rn.f32x2 operands are aligned SMEM pairs.

#define ROWP 132   // padded row stride in floats (528B = 33*16B)
#define TH   8     // H rows per CTA

typedef unsigned long long u64;

__constant__ __align__(16) u64 cW[1728];     // splatted (w,w), [(ci*3+kd)*3+kh][kw*8+co]
__device__   __align__(16) u64 gW_buf[1728]; // staging buffer for the memcpy node

__device__ __forceinline__ void fma2(u64& d, u64 a, u64 b) {
    asm("fma.rn.f32x2 %0, %1, %2, %0;" : "+l"(d) : "l"(a), "l"(b));
}
__device__ __forceinline__ u64 pk2(float lo, float hi) {
    u64 r;
    asm("mov.b64 %0, {%1, %2};" : "=l"(r) : "f"(lo), "f"(hi));
    return r;
}
__device__ __forceinline__ float2 up2(u64 v) {
    float lo, hi;
    asm("mov.b64 {%0, %1}, %2;" : "=f"(lo), "=f"(hi) : "l"(v));
    return make_float2(lo, hi);
}

// sigmoid(gelu_tanh(relu(y))): for yr=relu(y)>=0,
//   gelu = 0.5*yr*(1+tanh(t)) = yr * sigmoid(2t),  t = 0.79788456*(yr + 0.044715*yr^3)
__device__ __forceinline__ float act_chain(float y) {
    float yr = fmaxf(y, 0.0f);
    float q  = fmaf(0.044715f * yr, yr, 1.0f);
    float t2 = 1.5957691216057308f * yr * q;          // 2*t
    float g  = yr * __fdividef(1.0f, 1.0f + __expf(-t2));
    return __fdividef(1.0f, 1.0f + __expf(-g));
}

__global__ void weight_splat_kernel(const float* __restrict__ wgt) {
    for (int i = threadIdx.x; i < 1728; i += 256) {
        int co  = i / 216;  int rem = i - co * 216;
        int ci  = rem / 27; int r2  = rem - ci * 27;
        int kd  = r2 / 9;   int r3  = r2 - kd * 9;
        int kh  = r3 / 3;   int kw  = r3 - kh * 3;
        float w = wgt[i];   // layout [co][ci][kd][kh][kw] linear == i
        gW_buf[((ci * 3 + kd) * 3 + kh) * 24 + kw * 8 + co] = pk2(w, w);
    }
}

__global__ void __launch_bounds__(128, 4)
conv3d_fused_kernel(const float* __restrict__ x,
                    const float* __restrict__ bias,
                    float* __restrict__ out)
{
    __shared__ __align__(16) float sC[(TH + 2) * ROWP];   // sC[r][w] = x[r][w]
    __shared__ __align__(16) float sS[(TH + 2) * ROWP];   // sS[r][k] = x[r][k-1]

    const int tid  = threadIdx.x;
    const int lane = tid & 31;
    const int bx   = blockIdx.x;
    const int ht   = bx & 15;           // 16 H tiles of 8 rows
    const int dpos = (bx >> 4) & 31;
    const int b    = bx >> 9;
    const int h0   = ht << 3;

    // k=129 pad of the shifted copy (never rewritten; k=0 written each slab)
    if (tid < TH + 2) sS[tid * ROWP + 129] = 0.0f;

    const int hh = tid >> 4;     // row in tile (0..7)
    const int wg = tid & 15;
    const int w0 = wg << 3;

    u64 acc[32];
    #pragma unroll
    for (int k = 0; k < 32; ++k) acc[k] = 0ull;

    for (int ci = 0; ci < 8; ++ci) {
        const float* xb = x + ((size_t)((b * 8 + ci) * 32) << 14);
        #pragma unroll 1
        for (int dz = 0; dz < 3; ++dz) {
            const int dd = dpos + dz - 1;
            if ((unsigned)dd >= 32u) continue;   // zero slice contributes nothing

            __syncthreads();  // previous slab fully consumed

            // single-pass staging: (TH+2) rows x 128 cols; each warp stages a
            // full row per iteration (lane == float4 column), writing sC and
            // the lane-rotated sS in the same pass.
            const float4* xs4 = reinterpret_cast<const float4*>(xb + ((size_t)dd << 14));
            #pragma unroll
            for (int j = 0; j < 3; ++j) {
                int i = tid + j * 128;           // 0..383, valid < 320
                int hz = i >> 5;                 // uniform within a warp
                bool rowok = hz < TH + 2;
                int hg = h0 + hz - 1;
                float4 v = make_float4(0.f, 0.f, 0.f, 0.f);
                if (rowok && (unsigned)hg < 128u) v = xs4[(hg << 5) + lane];
                float pw = __shfl_up_sync(0xffffffffu, v.w, 1);
                if (lane == 0) pw = 0.0f;        // x[-1] zero pad
                if (rowok) {
                    float* rowC = &sC[hz * ROWP];
                    float* rowS = &sS[hz * ROWP];
                    *reinterpret_cast<float4*>(rowC + (lane << 2)) = v;
                    *reinterpret_cast<float4*>(rowS + (lane << 2)) =
                        make_float4(pw, v.x, v.y, v.z);
                    if (lane == 31) rowS[128] = v.w;   // sS[128] = x[127]
                }
            }
            __syncthreads();

            #pragma unroll
            for (int kh = 0; kh < 3; ++kh) {
                const int roff = (hh + kh) * ROWP;
                const ulonglong2* cp = reinterpret_cast<const ulonglong2*>(&sC[roff + w0]);
                ulonglong2 ca = cp[0];    // center pairs 0,1
                ulonglong2 cb = cp[1];    // center pairs 2,3
                const ulonglong2* sp = reinterpret_cast<const ulonglong2*>(&sS[roff + w0]);
                ulonglong2 sa = sp[0];    // left pairs 0,1
                ulonglong2 sb = sp[1];    // left pairs 2,3
                u64 sr3 = *reinterpret_cast<const u64*>(&sS[roff + w0 + 8]); // right pair 3

                const u64* wp = &cW[((ci * 3 + dz) * 3 + kh) * 24];
                #pragma unroll
                for (int cp2 = 0; cp2 < 4; ++cp2) {   // co pairs (2 couts each)
                    ulonglong2 wL = *reinterpret_cast<const ulonglong2*>(wp + 2 * cp2);
                    ulonglong2 wC = *reinterpret_cast<const ulonglong2*>(wp + 8 + 2 * cp2);
                    ulonglong2 wR = *reinterpret_cast<const ulonglong2*>(wp + 16 + 2 * cp2);
                    u64* a0 = &acc[(2 * cp2) * 4];
                    u64* a1 = &acc[(2 * cp2 + 1) * 4];
                    fma2(a0[0], sa.x, wL.x);  fma2(a0[1], sa.y, wL.x);
                    fma2(a0[2], sb.x, wL.x);  fma2(a0[3], sb.y, wL.x);
                    fma2(a0[0], ca.x, wC.x);  fma2(a0[1], ca.y, wC.x);
                    fma2(a0[2], cb.x, wC.x);  fma2(a0[3], cb.y, wC.x);
                    fma2(a0[0], sa.y, wR.x);  fma2(a0[1], sb.x, wR.x);
                    fma2(a0[2], sb.y, wR.x);  fma2(a0[3], sr3, wR.x);
                    fma2(a1[0], sa.x, wL.y);  fma2(a1[1], sa.y, wL.y);
                    fma2(a1[2], sb.x, wL.y);  fma2(a1[3], sb.y, wL.y);
                    fma2(a1[0], ca.x, wC.y);  fma2(a1[1], ca.y, wC.y);
                    fma2(a1[2], cb.x, wC.y);  fma2(a1[3], cb.y, wC.y);
                    fma2(a1[0], sa.y, wR.y);  fma2(a1[1], sb.x, wR.y);
                    fma2(a1[2], sb.y, wR.y);  fma2(a1[3], sr3, wR.y);
                }
            }
        }
    }

    // --- epilogue: activation chain + bias, vectorized coalesced stores ---
    const int hout = h0 + hh;
    #pragma unroll
    for (int co = 0; co < 8; ++co) {
        float bb = bias[co];
        float o[8];
        #pragma unroll
        for (int j = 0; j < 4; ++j) {
            float2 p = up2(acc[co * 4 + j]);
            o[2 * j]     = p.x;
            o[2 * j + 1] = p.y;
        }
        #pragma unroll
        for (int k = 0; k < 8; ++k)
            o[k] = act_chain(o[k]) + bb;

        float4* dst = reinterpret_cast<float4*>(
            out + ((size_t)((b * 8 + co) * 32 + dpos) << 14) + (hout << 7) + w0);
        dst[0] = make_float4(o[0], o[1], o[2], o[3]);
        dst[1] = make_float4(o[4], o[5], o[6], o[7]);
    }
}

extern "C" void kernel_launch(void* const* d_in, const int* in_sizes, int n_in,
                              void* d_out, int out_size)
{
    const float* x    = (const float*)d_in[0];   // (8,8,32,128,128)
    const float* wgt  = (const float*)d_in[1];   // (8,8,3,3,3)
    const float* bias = (const float*)d_in[2];   // (8,1,1,1)
    float* out = (float*)d_out;                  // (8,8,32,128,128)

    weight_splat_kernel<<<1, 256>>>(wgt);
    void* gw_ptr = nullptr;
    cudaGetSymbolAddress(&gw_ptr, gW_buf);
    cudaMemcpyToSymbolAsync(cW, gw_ptr, 1728 * sizeof(u64), 0,
                            cudaMemcpyDeviceToDevice, 0);
    // grid = 16 H-tiles * 32 depths * 8 batches = 4096 blocks of 128 threads
    conv3d_fused_kernel<<<4096, 128>>>(x, bias, out);
}